// round 9
// baseline (speedup 1.0000x reference)
#include <cuda_runtime.h>
#include <cuda_bf16.h>
#include <cstdint>
#include <math.h>

#define B_ 32
#define S_ 512
#define F_ 512
#define T_ 1024

#define BM 128
#define BN 256
#define BK 32
// stage: Ah 8K | Al 8K | Bh 16K | Bl 16K = 48KB; 3 stages = 144KB; 1 CTA/SM, 512 thr
#define STAGE_B 49152
#define NSTAGE  3
#define GEMM_SMEM (NSTAGE * STAGE_B)

// ---------------- scratch (allocation-free) ----------------
__device__ __nv_bfloat16 g_zhT_hi[(size_t)B_*T_*S_];
__device__ __nv_bfloat16 g_zhT_lo[(size_t)B_*T_*S_];
__device__ __nv_bfloat16 g_zrT_hi[(size_t)B_*T_*S_];
__device__ __nv_bfloat16 g_zrT_lo[(size_t)B_*T_*S_];
__device__ __nv_bfloat16 g_auxT_hi[(size_t)B_*T_*S_];
__device__ __nv_bfloat16 g_auxT_lo[(size_t)B_*T_*S_];
__device__ __nv_bfloat16 g_C_hi[(size_t)B_*T_*T_];
__device__ __nv_bfloat16 g_C_lo[(size_t)B_*T_*T_];
__device__ __nv_bfloat16 g_a2_hi[(size_t)B_*F_*T_];
__device__ __nv_bfloat16 g_a2_lo[(size_t)B_*F_*T_];
__device__ float g_a3[(size_t)B_*F_*T_];
__device__ __nv_bfloat16 g_Wb_hi[S_*S_], g_Wb_lo[S_*S_];
__device__ __nv_bfloat16 g_Wq_hi[F_*S_], g_Wq_lo[F_*S_];
__device__ __nv_bfloat16 g_Wv_hi[F_*S_], g_Wv_lo[F_*S_];
__device__ float g_logit[B_*T_];

// ---------------- helpers ----------------
static __device__ __forceinline__ uint32_t s2u(const void* p){
    uint32_t a;
    asm("{ .reg .u64 t; cvta.to.shared.u64 t, %1; cvt.u32.u64 %0, t; }" : "=r"(a) : "l"(p));
    return a;
}
static __device__ __forceinline__ void cp16(uint32_t dst, const void* src){
    asm volatile("cp.async.cg.shared.global [%0], [%1], 16;" :: "r"(dst), "l"(src) : "memory");
}
static __device__ __forceinline__ void cp_commit(){
    asm volatile("cp.async.commit_group;" ::: "memory");
}
static __device__ __forceinline__ void ldm_x4(uint32_t& r0, uint32_t& r1, uint32_t& r2, uint32_t& r3, uint32_t a){
    asm volatile("ldmatrix.sync.aligned.m8n8.x4.shared.b16 {%0,%1,%2,%3}, [%4];"
                 : "=r"(r0), "=r"(r1), "=r"(r2), "=r"(r3) : "r"(a));
}
static __device__ __forceinline__ void mma16816(float* d, const uint32_t* a, const uint32_t* b){
    asm volatile("mma.sync.aligned.m16n8k16.row.col.f32.bf16.bf16.f32 "
                 "{%0,%1,%2,%3}, {%4,%5,%6,%7}, {%8,%9}, {%0,%1,%2,%3};"
                 : "+f"(d[0]), "+f"(d[1]), "+f"(d[2]), "+f"(d[3])
                 : "r"(a[0]), "r"(a[1]), "r"(a[2]), "r"(a[3]), "r"(b[0]), "r"(b[1]));
}

enum { EPI_NONE = 0, EPI_HILO = 1, EPI_TANH_HILO = 2, EPI_WG_RED = 3 };

// Swizzle: 64B rows, 4x16B chunks; chunk' = chunk ^ ((row>>1)&3).
// Conflict-free for cp.async stores and every ldmatrix phase (r7-verified).

// ---------------------------------------------------------------------------
// Mainloop: bf16 mma.sync, 3-term hi/lo compensation, BK=32, 3-stage cp.async,
// 512 threads (16 warps, 4/SMSP), one __syncthreads per K-iteration,
// fully hoisted swizzled addresses.
// ---------------------------------------------------------------------------
template <int KK>
static __device__ __forceinline__ void gemm_main(
    const __nv_bfloat16* __restrict__ pAh, const __nv_bfloat16* __restrict__ pAl,
    const __nv_bfloat16* __restrict__ pBh, const __nv_bfloat16* __restrict__ pBl,
    uint32_t sb, int tid, int m0, int n0, float (&acc)[4][4][4])
{
    const int wid = tid >> 5, lane = tid & 31;

    // ---- loader: row rC = tid>>2 (0..127), chunk cC = tid&3; 6 units/thread
    const int rC = tid >> 2, cC = tid & 3;
    const uint32_t soff = (uint32_t)(rC * 64 + ((cC ^ ((rC >> 1) & 3)) * 16));
    const __nv_bfloat16* gAh = pAh + (size_t)(m0 + rC) * KK + cC * 8;
    const __nv_bfloat16* gAl = pAl + (size_t)(m0 + rC) * KK + cC * 8;
    const __nv_bfloat16* gBh = pBh + (size_t)(n0 + rC) * KK + cC * 8;
    const __nv_bfloat16* gBl = pBl + (size_t)(n0 + rC) * KK + cC * 8;
    const size_t bStep = (size_t)128 * KK;

    auto cp_stage = [&](uint32_t st, int ko) {
        cp16(sb + st + soff,          gAh + ko);
        cp16(sb + st + 8192 + soff,   gAl + ko);
        cp16(sb + st + 16384 + soff,  gBh + ko);
        cp16(sb + st + 24576 + soff,  gBh + bStep + ko);
        cp16(sb + st + 32768 + soff,  gBl + ko);
        cp16(sb + st + 40960 + soff,  gBl + bStep + ko);
        cp_commit();
    };

    // ---- ldmatrix addresses, fully hoisted (warp tile 64x32) ----
    const int wm = (wid >> 3) * 64;      // 0 / 64
    const int wn = (wid & 7) * 32;       // 0..224
    uint32_t a_adr[4][2];
    const int acb = lane >> 4;
#pragma unroll
    for (int mf = 0; mf < 4; mf++) {
        int row = wm + mf * 16 + (lane & 15);
        int sw = (row >> 1) & 3;
#pragma unroll
        for (int ks = 0; ks < 2; ks++)
            a_adr[mf][ks] = sb + row * 64 + (uint32_t)(((acb + 2 * ks) ^ sw) << 4);
    }
    uint32_t b_adr[2][2];
    const int bcb = (lane >> 3) & 1;
#pragma unroll
    for (int nt = 0; nt < 2; nt++) {
        int row = wn + nt * 16 + (lane & 7) + ((lane & 16) >> 1);
        int sw = (row >> 1) & 3;
#pragma unroll
        for (int ks = 0; ks < 2; ks++)
            b_adr[nt][ks] = sb + 16384 + row * 64 + (uint32_t)(((bcb + 2 * ks) ^ sw) << 4);
    }

    const int NC = KK / BK;

    // prologue: stages 0, 1
    cp_stage(0, 0);
    cp_stage(STAGE_B, BK);

    int buf = 0, nbuf = 2;
    for (int i = 0; i < NC; i++) {
        if (i + 1 < NC) asm volatile("cp.async.wait_group 1;" ::: "memory");
        else            asm volatile("cp.async.wait_group 0;" ::: "memory");
        __syncthreads();

        if (i + 2 < NC) cp_stage((uint32_t)nbuf * STAGE_B, (i + 2) * BK);

        const uint32_t stg = (uint32_t)buf * STAGE_B;
#pragma unroll
        for (int ks = 0; ks < 2; ks++) {
            uint32_t bh[4][2], bl[4][2];
#pragma unroll
            for (int nt = 0; nt < 2; nt++) {
                const uint32_t ad = b_adr[nt][ks] + stg;
                ldm_x4(bh[nt*2][0], bh[nt*2][1], bh[nt*2+1][0], bh[nt*2+1][1], ad);
                ldm_x4(bl[nt*2][0], bl[nt*2][1], bl[nt*2+1][0], bl[nt*2+1][1], ad + 16384);
            }
            uint32_t ah[4], ahn[4], al[4];
            ldm_x4(ah[0], ah[1], ah[2], ah[3], a_adr[0][ks] + stg);
#pragma unroll
            for (int mf = 0; mf < 4; mf++) {
                if (mf + 1 < 4)
                    ldm_x4(ahn[0], ahn[1], ahn[2], ahn[3], a_adr[mf+1][ks] + stg);
#pragma unroll
                for (int nf = 0; nf < 4; nf++) mma16816(acc[mf][nf], ah, bh[nf]);
                ldm_x4(al[0], al[1], al[2], al[3], a_adr[mf][ks] + 8192 + stg);
#pragma unroll
                for (int nf = 0; nf < 4; nf++) mma16816(acc[mf][nf], ah, bl[nf]);
#pragma unroll
                for (int nf = 0; nf < 4; nf++) mma16816(acc[mf][nf], al, bh[nf]);
#pragma unroll
                for (int q = 0; q < 4; q++) ah[q] = ahn[q];
            }
        }
        buf = (buf == 2) ? 0 : buf + 1;
        nbuf = (nbuf == 2) ? 0 : nbuf + 1;
    }
}

// ---------------------------------------------------------------------------
// Merged kernel: G1 + G3 + G4 (independent, K=512). 512 CTAs per gemm.
// ---------------------------------------------------------------------------
struct MultiDesc {
    const __nv_bfloat16* Ah[3]; const __nv_bfloat16* Al[3];
    const __nv_bfloat16* Bh[3]; const __nv_bfloat16* Bl[3];
    float* Dout[3]; __nv_bfloat16* Dhi[3]; __nv_bfloat16* Dlo[3];
    long sA[3], sB[3], sD[3];
    int N[3], gxlog[3], epi[3];
};

__global__ __launch_bounds__(512, 1)
void mma_multi(MultiDesc d)
{
    extern __shared__ char smem[];
    const uint32_t sb = s2u(smem);
    const int tid = threadIdx.x;
    const int x = blockIdx.x;
    const int gid = x >> 9;              // 512 CTAs per gemm
    const int rem = x & 511;
    const int b = rem >> 4;
    const int t = rem & 15;
    const int gxl = d.gxlog[gid];
    const int bx = t & ((1 << gxl) - 1);
    const int by = t >> gxl;
    const int m0 = by * BM, n0 = bx * BN;
    const int N = d.N[gid];

    float acc[4][4][4];
#pragma unroll
    for (int i = 0; i < 4; i++)
#pragma unroll
        for (int j = 0; j < 4; j++)
#pragma unroll
            for (int q = 0; q < 4; q++) acc[i][j][q] = 0.0f;

    gemm_main<512>(d.Ah[gid] + (size_t)b * d.sA[gid], d.Al[gid] + (size_t)b * d.sA[gid],
                   d.Bh[gid] + (size_t)b * d.sB[gid], d.Bl[gid] + (size_t)b * d.sB[gid],
                   sb, tid, m0, n0, acc);

    const int wid = tid >> 5, lane = tid & 31;
    const int wm = (wid >> 3) * 64, wn = (wid & 7) * 32;
    const int g = lane >> 2, tg = lane & 3;
    const int epi = d.epi[gid];
    const long sD = d.sD[gid];

#pragma unroll
    for (int mf = 0; mf < 4; mf++) {
#pragma unroll
        for (int h = 0; h < 2; h++) {
            const int row = m0 + wm + mf * 16 + g + h * 8;
            const size_t rowoff = (size_t)b * sD + (size_t)row * N;
#pragma unroll
            for (int nf = 0; nf < 4; nf++) {
                const int col = n0 + wn + nf * 8 + tg * 2;
                float d0 = acc[mf][nf][h * 2 + 0];
                float d1 = acc[mf][nf][h * 2 + 1];
                if (epi == EPI_NONE) {
                    *(float2*)(d.Dout[gid] + rowoff + col) = make_float2(d0, d1);
                } else {
                    __nv_bfloat16 h0 = __float2bfloat16(d0), h1 = __float2bfloat16(d1);
                    __nv_bfloat16 l0 = __float2bfloat16(d0 - __bfloat162float(h0));
                    __nv_bfloat16 l1 = __float2bfloat16(d1 - __bfloat162float(h1));
                    *(uint32_t*)(d.Dhi[gid] + rowoff + col) =
                        (uint32_t)__bfloat16_as_ushort(h0) | ((uint32_t)__bfloat16_as_ushort(h1) << 16);
                    *(uint32_t*)(d.Dlo[gid] + rowoff + col) =
                        (uint32_t)__bfloat16_as_ushort(l0) | ((uint32_t)__bfloat16_as_ushort(l1) << 16);
                }
            }
        }
    }
}

// ---------------------------------------------------------------------------
// Single-GEMM kernel for G2 (TANH_HILO, K=512) and G5 (WG_RED, K=1024).
// ---------------------------------------------------------------------------
template <int EPI, int KK>
__global__ __launch_bounds__(512, 1)
void mma_gemm(const __nv_bfloat16* __restrict__ Ahi, const __nv_bfloat16* __restrict__ Alo,
              const __nv_bfloat16* __restrict__ Bhi, const __nv_bfloat16* __restrict__ Blo,
              float* __restrict__ Dout,
              __nv_bfloat16* __restrict__ Dhi, __nv_bfloat16* __restrict__ Dlo,
              const float* __restrict__ Eadd, const float* __restrict__ wv,
              int N, long sA, long sB, long sD, long sE)
{
    extern __shared__ char smem[];
    const uint32_t sb = s2u(smem);
    const int tid = threadIdx.x;
    const int b = blockIdx.z;
    const int m0 = blockIdx.y * BM, n0 = blockIdx.x * BN;

    float acc[4][4][4];
#pragma unroll
    for (int i = 0; i < 4; i++)
#pragma unroll
        for (int j = 0; j < 4; j++)
#pragma unroll
            for (int q = 0; q < 4; q++) acc[i][j][q] = 0.0f;

    gemm_main<KK>(Ahi + (size_t)b * sA, Alo + (size_t)b * sA,
                  Bhi + (size_t)b * sB, Blo + (size_t)b * sB,
                  sb, tid, m0, n0, acc);

    const int wid = tid >> 5, lane = tid & 31;
    const int wm = (wid >> 3) * 64, wn = (wid & 7) * 32;
    const int g = lane >> 2, tg = lane & 3;

    if (EPI == EPI_TANH_HILO) {
#pragma unroll
        for (int mf = 0; mf < 4; mf++) {
#pragma unroll
            for (int h = 0; h < 2; h++) {
                const int row = m0 + wm + mf * 16 + g + h * 8;
                const size_t rowoff = (size_t)b * sD + (size_t)row * N;
#pragma unroll
                for (int nf = 0; nf < 4; nf++) {
                    const int col = n0 + wn + nf * 8 + tg * 2;
                    float d0 = tanhf(acc[mf][nf][h * 2 + 0]);
                    float d1 = tanhf(acc[mf][nf][h * 2 + 1]);
                    __nv_bfloat16 h0 = __float2bfloat16(d0), h1 = __float2bfloat16(d1);
                    __nv_bfloat16 l0 = __float2bfloat16(d0 - __bfloat162float(h0));
                    __nv_bfloat16 l1 = __float2bfloat16(d1 - __bfloat162float(h1));
                    *(uint32_t*)(Dhi + rowoff + col) =
                        (uint32_t)__bfloat16_as_ushort(h0) | ((uint32_t)__bfloat16_as_ushort(h1) << 16);
                    *(uint32_t*)(Dlo + rowoff + col) =
                        (uint32_t)__bfloat16_as_ushort(l0) | ((uint32_t)__bfloat16_as_ushort(l1) << 16);
                    *(float2*)(Dout + rowoff + col) = make_float2(d0, d1);
                }
            }
        }
    } else {
        // EPI_WG_RED: logits[b, n] += sum_rows w_hq[row] * tanh(acc + a3[row][n])
        float colsum[8];
#pragma unroll
        for (int q = 0; q < 8; q++) colsum[q] = 0.0f;
#pragma unroll
        for (int mf = 0; mf < 4; mf++) {
#pragma unroll
            for (int h = 0; h < 2; h++) {
                const int row = m0 + wm + mf * 16 + g + h * 8;
                const float w = wv[row];
                const float* ep = Eadd + (size_t)b * sE + (size_t)row * N;
#pragma unroll
                for (int nf = 0; nf < 4; nf++) {
                    const int col = n0 + wn + nf * 8 + tg * 2;
                    const float2 e = *(const float2*)(ep + col);
                    colsum[nf*2+0] += w * tanhf(acc[mf][nf][h * 2 + 0] + e.x);
                    colsum[nf*2+1] += w * tanhf(acc[mf][nf][h * 2 + 1] + e.y);
                }
            }
        }
        __syncthreads();
        float* red = (float*)smem;
        if (tid < BN) red[tid] = 0.0f;
        __syncthreads();
#pragma unroll
        for (int nf = 0; nf < 4; nf++) {
            atomicAdd(&red[wn + nf * 8 + tg * 2 + 0], colsum[nf*2+0]);
            atomicAdd(&red[wn + nf * 8 + tg * 2 + 1], colsum[nf*2+1]);
        }
        __syncthreads();
        if (tid < BN) atomicAdd(&g_logit[b * T_ + n0 + tid], red[tid]);
    }
}

// ---------------- transpose + bf16 hi/lo split (both z tensors) ----------------
__global__ void transconv2_k(const float* __restrict__ Zh, const float* __restrict__ Zr)
{
    __shared__ float tile[32][33];
    const int bz = blockIdx.z;
    const int which = bz >> 5;
    const int bb = bz & 31;
    const float* Xb = ((which == 0) ? Zh : Zr) + (size_t)bb * S_ * T_;
    __nv_bfloat16* H = ((which == 0) ? g_zhT_hi : g_zrT_hi) + (size_t)bb * T_ * S_;
    __nv_bfloat16* L = ((which == 0) ? g_zhT_lo : g_zrT_lo) + (size_t)bb * T_ * S_;
    const int x0 = blockIdx.x * 32, y0 = blockIdx.y * 32;
    const int tx = threadIdx.x, ty = threadIdx.y;
#pragma unroll
    for (int j = 0; j < 4; j++)
        tile[ty + j * 8][tx] = Xb[(size_t)(y0 + ty + j * 8) * T_ + x0 + tx];
    __syncthreads();
#pragma unroll
    for (int j = 0; j < 4; j++) {
        float v = tile[tx][ty + j * 8];
        size_t o = (size_t)(x0 + ty + j * 8) * S_ + y0 + tx;
        __nv_bfloat16 h = __float2bfloat16(v);
        H[o] = h;
        L[o] = __float2bfloat16(v - __bfloat162float(h));
    }
}

__global__ void wconv_all_k(const float* __restrict__ Wb, const float* __restrict__ Wq,
                            const float* __restrict__ Wv)
{
    int i = blockIdx.x * blockDim.x + threadIdx.x;
    int which = blockIdx.y;
    const float* X = (which == 0) ? Wb : (which == 1) ? Wq : Wv;
    __nv_bfloat16* H = (which == 0) ? g_Wb_hi : (which == 1) ? g_Wq_hi : g_Wv_hi;
    __nv_bfloat16* L = (which == 0) ? g_Wb_lo : (which == 1) ? g_Wq_lo : g_Wv_lo;
    float v = X[i];
    __nv_bfloat16 h = __float2bfloat16(v);
    H[i] = h;
    L[i] = __float2bfloat16(v - __bfloat162float(h));
    if (which == 0 && i < B_ * T_) g_logit[i] = 0.0f;
}

__global__ void softmax_k(float* __restrict__ aq)
{
    __shared__ float sm[256];
    int b = blockIdx.x, tid = threadIdx.x;
    const float* lg = g_logit + b * T_;
    float v[4]; float vmax = -1e30f;
#pragma unroll
    for (int i = 0; i < 4; i++) { v[i] = lg[tid + i * 256]; vmax = fmaxf(vmax, v[i]); }
    sm[tid] = vmax; __syncthreads();
    for (int s = 128; s > 0; s >>= 1) { if (tid < s) sm[tid] = fmaxf(sm[tid], sm[tid + s]); __syncthreads(); }
    vmax = sm[0]; __syncthreads();
    float lsum = 0.0f;
#pragma unroll
    for (int i = 0; i < 4; i++) { v[i] = expf(v[i] - vmax); lsum += v[i]; }
    sm[tid] = lsum; __syncthreads();
    for (int s = 128; s > 0; s >>= 1) { if (tid < s) sm[tid] += sm[tid + s]; __syncthreads(); }
    float inv = 1.0f / sm[0];
#pragma unroll
    for (int i = 0; i < 4; i++) aq[b * T_ + tid + i * 256] = v[i] * inv;
}

__global__ void attn_k(const float* __restrict__ zr, const float* __restrict__ aq,
                       float* __restrict__ out)
{
    int gwarp = (blockIdx.x * blockDim.x + threadIdx.x) >> 5;
    int lane = threadIdx.x & 31;
    int b = gwarp >> 9, s = gwarp & (S_ - 1);
    const float* z = zr + ((size_t)b * S_ + s) * T_;
    const float* a = aq + b * T_;
    float acc = 0.0f;
#pragma unroll 4
    for (int t = lane; t < T_; t += 32) acc += z[t] * a[t];
#pragma unroll
    for (int o = 16; o > 0; o >>= 1) acc += __shfl_xor_sync(0xFFFFFFFFu, acc, o);
    if (lane == 0) out[b * S_ + s] = acc;
}

extern "C" void kernel_launch(void* const* d_in, const int* in_sizes, int n_in,
                              void* d_out, int out_size)
{
    const float* zr  = (const float*)d_in[0];
    const float* zh  = (const float*)d_in[1];
    const float* Wb  = (const float*)d_in[2];
    const float* Wq  = (const float*)d_in[3];
    const float* Wv  = (const float*)d_in[4];
    const float* whq = (const float*)d_in[5];

    float* out  = (float*)d_out;
    float* attn = out;
    float* aq   = out + B_ * S_;
    float* Cmat = out + B_ * S_ + B_ * T_;

    cudaFuncSetAttribute(mma_multi, cudaFuncAttributeMaxDynamicSharedMemorySize, GEMM_SMEM);
    cudaFuncSetAttribute(mma_gemm<EPI_TANH_HILO, 512>,  cudaFuncAttributeMaxDynamicSharedMemorySize, GEMM_SMEM);
    cudaFuncSetAttribute(mma_gemm<EPI_WG_RED, 1024>,    cudaFuncAttributeMaxDynamicSharedMemorySize, GEMM_SMEM);

    __nv_bfloat16 *zhT_hi, *zhT_lo, *zrT_hi, *zrT_lo, *auxT_hi, *auxT_lo;
    __nv_bfloat16 *C_hi, *C_lo, *a2_hi, *a2_lo;
    __nv_bfloat16 *Wb_hi, *Wb_lo, *Wq_hi, *Wq_lo, *Wv_hi, *Wv_lo;
    float *a3;
    cudaGetSymbolAddress((void**)&zhT_hi, g_zhT_hi);   cudaGetSymbolAddress((void**)&zhT_lo, g_zhT_lo);
    cudaGetSymbolAddress((void**)&zrT_hi, g_zrT_hi);   cudaGetSymbolAddress((void**)&zrT_lo, g_zrT_lo);
    cudaGetSymbolAddress((void**)&auxT_hi, g_auxT_hi); cudaGetSymbolAddress((void**)&auxT_lo, g_auxT_lo);
    cudaGetSymbolAddress((void**)&C_hi, g_C_hi);       cudaGetSymbolAddress((void**)&C_lo, g_C_lo);
    cudaGetSymbolAddress((void**)&a2_hi, g_a2_hi);     cudaGetSymbolAddress((void**)&a2_lo, g_a2_lo);
    cudaGetSymbolAddress((void**)&Wb_hi, g_Wb_hi);     cudaGetSymbolAddress((void**)&Wb_lo, g_Wb_lo);
    cudaGetSymbolAddress((void**)&Wq_hi, g_Wq_hi);     cudaGetSymbolAddress((void**)&Wq_lo, g_Wq_lo);
    cudaGetSymbolAddress((void**)&Wv_hi, g_Wv_hi);     cudaGetSymbolAddress((void**)&Wv_lo, g_Wv_lo);
    cudaGetSymbolAddress((void**)&a3, g_a3);

    const long TS = (long)T_ * S_;
    const long TT = (long)T_ * T_;
    const long FT = (long)F_ * T_;

    wconv_all_k<<<dim3((F_*S_)/256, 3), 256>>>(Wb, Wq, Wv);
    transconv2_k<<<dim3(T_/32, S_/32, 2*B_), dim3(32, 8)>>>(zh, zr);

    // Merged G1+G3+G4 (all K=512, independent); 512 CTAs each:
    //  G1: auxT[h][s] = sum_u zhT[h][u] * Wb[s][u]   M=1024 (8 by), N=512 (2 bx)
    //  G3: aux2[f][h] = sum_s Wv[f][s] * zhT[h][s]   M=512 (4 by),  N=1024 (4 bx)
    //  G4: aux3[f][t] = sum_s Wq[f][s] * zrT[t][s]   M=512 (4 by),  N=1024 (4 bx)
    MultiDesc md;
    md.Ah[0]=zhT_hi; md.Al[0]=zhT_lo; md.Bh[0]=Wb_hi;  md.Bl[0]=Wb_lo;
    md.Dout[0]=nullptr; md.Dhi[0]=auxT_hi; md.Dlo[0]=auxT_lo;
    md.sA[0]=TS; md.sB[0]=0; md.sD[0]=TS; md.N[0]=S_; md.gxlog[0]=1; md.epi[0]=EPI_HILO;

    md.Ah[1]=Wv_hi;  md.Al[1]=Wv_lo;  md.Bh[1]=zhT_hi; md.Bl[1]=zhT_lo;
    md.Dout[1]=nullptr; md.Dhi[1]=a2_hi; md.Dlo[1]=a2_lo;
    md.sA[1]=0; md.sB[1]=TS; md.sD[1]=FT; md.N[1]=T_; md.gxlog[1]=2; md.epi[1]=EPI_HILO;

    md.Ah[2]=Wq_hi;  md.Al[2]=Wq_lo;  md.Bh[2]=zrT_hi; md.Bl[2]=zrT_lo;
    md.Dout[2]=a3; md.Dhi[2]=nullptr; md.Dlo[2]=nullptr;
    md.sA[2]=0; md.sB[2]=TS; md.sD[2]=FT; md.N[2]=T_; md.gxlog[2]=2; md.epi[2]=EPI_NONE;

    mma_multi<<<3 * 512, 512, GEMM_SMEM>>>(md);

    // G2: C[t][h] = tanh( sum_s zrT[t][s] * auxT[h][s] )   M=N=1024, K=512
    mma_gemm<EPI_TANH_HILO, 512><<<dim3(T_/BN, T_/BM, B_), 512, GEMM_SMEM>>>(
        zrT_hi, zrT_lo, auxT_hi, auxT_lo, Cmat, C_hi, C_lo, nullptr, nullptr,
        T_, TS, TS, TT, 0L);

    // G5 fused: logits[b,t] = sum_f w_hq[f]*tanh(a3[f,t] + sum_h a2[f,h]*C[t,h])
    mma_gemm<EPI_WG_RED, 1024><<<dim3(T_/BN, F_/BM, B_), 512, GEMM_SMEM>>>(
        a2_hi, a2_lo, C_hi, C_lo, nullptr, nullptr, nullptr, a3, whq,
        T_, FT, TT, 0L, FT);

    softmax_k<<<B_, 256>>>(aq);
    attn_k<<<(B_ * S_ * 32) / 256, 256>>>(zr, aq, attn);
}

// round 10
// speedup vs baseline: 1.1391x; 1.1391x over previous
#include <cuda_runtime.h>
#include <cuda_bf16.h>
#include <cstdint>
#include <math.h>

#define B_ 32
#define S_ 512
#define F_ 512
#define T_ 1024

#define BM 128
#define BN 128
#define BK 32
// tile: 128 rows x 64B (swizzled, no pad) = 8KB; 4 tiles/stage; 3 stages = 96KB
#define TILE_B   8192
#define STAGE_B  (4 * TILE_B)
#define NSTAGE   3
#define GEMM_SMEM (NSTAGE * STAGE_B)

// ---------------- scratch (allocation-free) ----------------
__device__ __nv_bfloat16 g_zhT_hi[(size_t)B_*T_*S_];
__device__ __nv_bfloat16 g_zhT_lo[(size_t)B_*T_*S_];
__device__ __nv_bfloat16 g_zrT_hi[(size_t)B_*T_*S_];
__device__ __nv_bfloat16 g_zrT_lo[(size_t)B_*T_*S_];
__device__ __nv_bfloat16 g_auxT_hi[(size_t)B_*T_*S_];
__device__ __nv_bfloat16 g_auxT_lo[(size_t)B_*T_*S_];
__device__ __nv_bfloat16 g_C_hi[(size_t)B_*T_*T_];
__device__ __nv_bfloat16 g_C_lo[(size_t)B_*T_*T_];
__device__ __nv_bfloat16 g_a2_hi[(size_t)B_*F_*T_];
__device__ __nv_bfloat16 g_a2_lo[(size_t)B_*F_*T_];
__device__ float g_a3[(size_t)B_*F_*T_];
__device__ __nv_bfloat16 g_Wb_hi[S_*S_], g_Wb_lo[S_*S_];
__device__ __nv_bfloat16 g_Wq_hi[F_*S_], g_Wq_lo[F_*S_];
__device__ __nv_bfloat16 g_Wv_hi[F_*S_], g_Wv_lo[F_*S_];
__device__ float g_logit[B_*T_];

// ---------------- helpers ----------------
static __device__ __forceinline__ uint32_t s2u(const void* p){
    uint32_t a;
    asm("{ .reg .u64 t; cvta.to.shared.u64 t, %1; cvt.u32.u64 %0, t; }" : "=r"(a) : "l"(p));
    return a;
}
static __device__ __forceinline__ void cp16(uint32_t dst, const void* src){
    asm volatile("cp.async.cg.shared.global [%0], [%1], 16;" :: "r"(dst), "l"(src) : "memory");
}
static __device__ __forceinline__ void cp_commit(){
    asm volatile("cp.async.commit_group;" ::: "memory");
}
static __device__ __forceinline__ void ldm_x4(uint32_t& r0, uint32_t& r1, uint32_t& r2, uint32_t& r3, uint32_t a){
    asm volatile("ldmatrix.sync.aligned.m8n8.x4.shared.b16 {%0,%1,%2,%3}, [%4];"
                 : "=r"(r0), "=r"(r1), "=r"(r2), "=r"(r3) : "r"(a));
}
static __device__ __forceinline__ void mma16816(float* d, const uint32_t* a, const uint32_t* b){
    asm volatile("mma.sync.aligned.m16n8k16.row.col.f32.bf16.bf16.f32 "
                 "{%0,%1,%2,%3}, {%4,%5,%6,%7}, {%8,%9}, {%0,%1,%2,%3};"
                 : "+f"(d[0]), "+f"(d[1]), "+f"(d[2]), "+f"(d[3])
                 : "r"(a[0]), "r"(a[1]), "r"(a[2]), "r"(a[3]), "r"(b[0]), "r"(b[1]));
}

enum { EPI_NONE = 0, EPI_HILO = 1, EPI_TANH_HILO = 2, EPI_WG_RED = 3 };

// Swizzle: 64B rows, 4x16B chunks; chunk' = chunk ^ ((row>>1)&3).
// Conflict-free for cp.async stores and every ldmatrix phase (r7-verified).

// ---------------------------------------------------------------------------
// Mainloop (r7 base): bf16 mma.sync, 3-term hi/lo compensation, BK=32,
// 3-stage cp.async, one __syncthreads per K-iteration.
// r10 changes: cp.async burst issued AFTER ks=0 fragment loads (off the LDSM
// critical path); fragment order B-hi -> A-hi(0) -> B-lo.
// ---------------------------------------------------------------------------
template <int KK>
static __device__ __forceinline__ void gemm_main(
    const __nv_bfloat16* __restrict__ sAh, const __nv_bfloat16* __restrict__ sAl,
    const __nv_bfloat16* __restrict__ sBh, const __nv_bfloat16* __restrict__ sBl,
    uint32_t sb, int tid, int m0, int n0, float (&acc)[4][4][4])
{
    const int wid = tid >> 5, lane = tid & 31;

    // loader geometry: 2048 16B units per stage (4 tiles x 512), 8 per thread
    const __nv_bfloat16* gsrc[8];
    uint32_t sdst[8];
#pragma unroll
    for (int u = 0; u < 8; u++) {
        int unit = tid + u * 256;
        int t = unit >> 9;
        int r = (unit >> 2) & 127;
        int c = unit & 3;
        const __nv_bfloat16* base = (t == 0) ? sAh : (t == 1) ? sAl : (t == 2) ? sBh : sBl;
        int row0 = (t < 2) ? m0 : n0;
        gsrc[u] = base + (size_t)(row0 + r) * KK + c * 8;
        sdst[u] = sb + t * TILE_B + r * 64 + ((c ^ ((r >> 1) & 3)) * 16);
    }

    const int wm = (wid >> 2) * 64;
    const int wn = (wid & 3) * 32;

    // ldmatrix row bases + per-row swizzle keys
    uint32_t a_row[4]; int a_sw[4];
    const int a_cb = lane >> 4;
#pragma unroll
    for (int mf = 0; mf < 4; mf++) {
        int row = wm + mf * 16 + (lane & 15);
        a_row[mf] = sb + row * 64;
        a_sw[mf] = (row >> 1) & 3;
    }
    uint32_t b_row[2]; int b_sw[2];
    const int b_cb = (lane >> 3) & 1;
#pragma unroll
    for (int nt = 0; nt < 2; nt++) {
        int row = wn + nt * 16 + (lane & 7) + ((lane & 16) >> 1);
        b_row[nt] = sb + row * 64;
        b_sw[nt] = (row >> 1) & 3;
    }

    const int NC = KK / BK;

    // prologue: stages 0, 1
#pragma unroll
    for (int u = 0; u < 8; u++) cp16(sdst[u], gsrc[u]);
    cp_commit();
#pragma unroll
    for (int u = 0; u < 8; u++) cp16(sdst[u] + STAGE_B, gsrc[u] + BK);
    cp_commit();

    int buf = 0, nbuf = 2;
    for (int i = 0; i < NC; i++) {
        if (i + 1 < NC) asm volatile("cp.async.wait_group 1;" ::: "memory");
        else            asm volatile("cp.async.wait_group 0;" ::: "memory");
        __syncthreads();   // stage-i data visible; frees buf (i-1)%3

        const uint32_t stg = (uint32_t)buf * STAGE_B;
#pragma unroll
        for (int ks = 0; ks < 2; ks++) {
            const int ac = a_cb + 2 * ks;
            const int bc = b_cb + 2 * ks;
            const uint32_t ba0 = b_row[0] + stg + (uint32_t)((bc ^ b_sw[0]) << 4);
            const uint32_t ba1 = b_row[1] + stg + (uint32_t)((bc ^ b_sw[1]) << 4);

            uint32_t bh[4][2], bl[4][2];
            // B-hi first (needed by first MMA), then A-hi(0), then B-lo
            ldm_x4(bh[0][0], bh[0][1], bh[1][0], bh[1][1], ba0 + 2 * TILE_B);
            ldm_x4(bh[2][0], bh[2][1], bh[3][0], bh[3][1], ba1 + 2 * TILE_B);
            uint32_t ah[4], ahn[4], al[4];
            ldm_x4(ah[0], ah[1], ah[2], ah[3],
                   a_row[0] + stg + (uint32_t)((ac ^ a_sw[0]) << 4));
            ldm_x4(bl[0][0], bl[0][1], bl[1][0], bl[1][1], ba0 + 3 * TILE_B);
            ldm_x4(bl[2][0], bl[2][1], bl[3][0], bl[3][1], ba1 + 3 * TILE_B);

            // cp.async for stage i+2: issued once per iter, after the critical
            // fragment loads so the LSU queue serves LDSM first.
            if (ks == 0 && i + 2 < NC) {
                const uint32_t dst = (uint32_t)nbuf * STAGE_B;
                const int koff = (i + 2) * BK;
#pragma unroll
                for (int u = 0; u < 8; u++) cp16(sdst[u] + dst, gsrc[u] + koff);
                cp_commit();
            }

#pragma unroll
            for (int mf = 0; mf < 4; mf++) {
                const uint32_t aadr = a_row[mf] + stg + (uint32_t)((ac ^ a_sw[mf]) << 4);
                if (mf + 1 < 4)
                    ldm_x4(ahn[0], ahn[1], ahn[2], ahn[3],
                           a_row[mf+1] + stg + (uint32_t)((ac ^ a_sw[mf+1]) << 4));
#pragma unroll
                for (int nf = 0; nf < 4; nf++) mma16816(acc[mf][nf], ah, bh[nf]);
                ldm_x4(al[0], al[1], al[2], al[3], aadr + TILE_B);
#pragma unroll
                for (int nf = 0; nf < 4; nf++) mma16816(acc[mf][nf], ah, bl[nf]);
#pragma unroll
                for (int nf = 0; nf < 4; nf++) mma16816(acc[mf][nf], al, bh[nf]);
#pragma unroll
                for (int q = 0; q < 4; q++) ah[q] = ahn[q];
            }
        }
        buf = (buf == 2) ? 0 : buf + 1;
        nbuf = (nbuf == 2) ? 0 : nbuf + 1;
    }
}

// ---------------------------------------------------------------------------
// Merged kernel: G1 + G3 + G4 (independent, K=512). 1024 CTAs per gemm.
// ---------------------------------------------------------------------------
struct MultiDesc {
    const __nv_bfloat16* Ah[3]; const __nv_bfloat16* Al[3];
    const __nv_bfloat16* Bh[3]; const __nv_bfloat16* Bl[3];
    float* Dout[3]; __nv_bfloat16* Dhi[3]; __nv_bfloat16* Dlo[3];
    long sA[3], sB[3], sD[3];
    int N[3], gxlog[3], epi[3];
};

__global__ __launch_bounds__(256, 2)
void mma_multi(MultiDesc d)
{
    extern __shared__ char smem[];
    const uint32_t sb = s2u(smem);
    const int tid = threadIdx.x;
    const int x = blockIdx.x;
    const int gid = x >> 10;
    const int rem = x & 1023;
    const int b = rem >> 5;
    const int t = rem & 31;
    const int gxl = d.gxlog[gid];
    const int bx = t & ((1 << gxl) - 1);
    const int by = t >> gxl;
    const int m0 = by * BM, n0 = bx * BN;
    const int N = d.N[gid];

    float acc[4][4][4];
#pragma unroll
    for (int i = 0; i < 4; i++)
#pragma unroll
        for (int j = 0; j < 4; j++)
#pragma unroll
            for (int q = 0; q < 4; q++) acc[i][j][q] = 0.0f;

    gemm_main<512>(d.Ah[gid] + (size_t)b * d.sA[gid], d.Al[gid] + (size_t)b * d.sA[gid],
                   d.Bh[gid] + (size_t)b * d.sB[gid], d.Bl[gid] + (size_t)b * d.sB[gid],
                   sb, tid, m0, n0, acc);

    const int wid = tid >> 5, lane = tid & 31;
    const int wm = (wid >> 2) * 64, wn = (wid & 3) * 32;
    const int g = lane >> 2, tg = lane & 3;
    const int epi = d.epi[gid];
    const long sD = d.sD[gid];

#pragma unroll
    for (int mf = 0; mf < 4; mf++) {
#pragma unroll
        for (int h = 0; h < 2; h++) {
            const int row = m0 + wm + mf * 16 + g + h * 8;
            const size_t rowoff = (size_t)b * sD + (size_t)row * N;
#pragma unroll
            for (int nf = 0; nf < 4; nf++) {
                const int col = n0 + wn + nf * 8 + tg * 2;
                float d0 = acc[mf][nf][h * 2 + 0];
                float d1 = acc[mf][nf][h * 2 + 1];
                if (epi == EPI_NONE) {
                    *(float2*)(d.Dout[gid] + rowoff + col) = make_float2(d0, d1);
                } else {
                    __nv_bfloat16 h0 = __float2bfloat16(d0), h1 = __float2bfloat16(d1);
                    __nv_bfloat16 l0 = __float2bfloat16(d0 - __bfloat162float(h0));
                    __nv_bfloat16 l1 = __float2bfloat16(d1 - __bfloat162float(h1));
                    *(uint32_t*)(d.Dhi[gid] + rowoff + col) =
                        (uint32_t)__bfloat16_as_ushort(h0) | ((uint32_t)__bfloat16_as_ushort(h1) << 16);
                    *(uint32_t*)(d.Dlo[gid] + rowoff + col) =
                        (uint32_t)__bfloat16_as_ushort(l0) | ((uint32_t)__bfloat16_as_ushort(l1) << 16);
                }
            }
        }
    }
}

// ---------------------------------------------------------------------------
// Single-GEMM kernel for G2 (TANH_HILO, K=512) and G5 (WG_RED, K=1024).
// ---------------------------------------------------------------------------
template <int EPI, int KK>
__global__ __launch_bounds__(256, 2)
void mma_gemm(const __nv_bfloat16* __restrict__ Ahi, const __nv_bfloat16* __restrict__ Alo,
              const __nv_bfloat16* __restrict__ Bhi, const __nv_bfloat16* __restrict__ Blo,
              float* __restrict__ Dout,
              __nv_bfloat16* __restrict__ Dhi, __nv_bfloat16* __restrict__ Dlo,
              const float* __restrict__ Eadd, const float* __restrict__ wv,
              int N, long sA, long sB, long sD, long sE)
{
    extern __shared__ char smem[];
    const uint32_t sb = s2u(smem);
    const int tid = threadIdx.x;
    const int b = blockIdx.z;
    const int m0 = blockIdx.y * BM, n0 = blockIdx.x * BN;

    float acc[4][4][4];
#pragma unroll
    for (int i = 0; i < 4; i++)
#pragma unroll
        for (int j = 0; j < 4; j++)
#pragma unroll
            for (int q = 0; q < 4; q++) acc[i][j][q] = 0.0f;

    gemm_main<KK>(Ahi + (size_t)b * sA, Alo + (size_t)b * sA,
                  Bhi + (size_t)b * sB, Blo + (size_t)b * sB,
                  sb, tid, m0, n0, acc);

    const int wid = tid >> 5, lane = tid & 31;
    const int wm = (wid >> 2) * 64, wn = (wid & 3) * 32;
    const int g = lane >> 2, tg = lane & 3;

    if (EPI == EPI_TANH_HILO) {
#pragma unroll
        for (int mf = 0; mf < 4; mf++) {
#pragma unroll
            for (int h = 0; h < 2; h++) {
                const int row = m0 + wm + mf * 16 + g + h * 8;
                const size_t rowoff = (size_t)b * sD + (size_t)row * N;
#pragma unroll
                for (int nf = 0; nf < 4; nf++) {
                    const int col = n0 + wn + nf * 8 + tg * 2;
                    float d0 = tanhf(acc[mf][nf][h * 2 + 0]);
                    float d1 = tanhf(acc[mf][nf][h * 2 + 1]);
                    __nv_bfloat16 h0 = __float2bfloat16(d0), h1 = __float2bfloat16(d1);
                    __nv_bfloat16 l0 = __float2bfloat16(d0 - __bfloat162float(h0));
                    __nv_bfloat16 l1 = __float2bfloat16(d1 - __bfloat162float(h1));
                    *(uint32_t*)(Dhi + rowoff + col) =
                        (uint32_t)__bfloat16_as_ushort(h0) | ((uint32_t)__bfloat16_as_ushort(h1) << 16);
                    *(uint32_t*)(Dlo + rowoff + col) =
                        (uint32_t)__bfloat16_as_ushort(l0) | ((uint32_t)__bfloat16_as_ushort(l1) << 16);
                    *(float2*)(Dout + rowoff + col) = make_float2(d0, d1);
                }
            }
        }
    } else {
        // EPI_WG_RED: logits[b, n] += sum_rows w_hq[row] * tanh(acc + a3[row][n])
        float colsum[8];
#pragma unroll
        for (int q = 0; q < 8; q++) colsum[q] = 0.0f;
#pragma unroll
        for (int mf = 0; mf < 4; mf++) {
#pragma unroll
            for (int h = 0; h < 2; h++) {
                const int row = m0 + wm + mf * 16 + g + h * 8;
                const float w = wv[row];
                const float* ep = Eadd + (size_t)b * sE + (size_t)row * N;
#pragma unroll
                for (int nf = 0; nf < 4; nf++) {
                    const int col = n0 + wn + nf * 8 + tg * 2;
                    const float2 e = *(const float2*)(ep + col);
                    colsum[nf*2+0] += w * tanhf(acc[mf][nf][h * 2 + 0] + e.x);
                    colsum[nf*2+1] += w * tanhf(acc[mf][nf][h * 2 + 1] + e.y);
                }
            }
        }
        __syncthreads();
        float* red = (float*)smem;
        if (tid < BN) red[tid] = 0.0f;
        __syncthreads();
#pragma unroll
        for (int nf = 0; nf < 4; nf++) {
            atomicAdd(&red[wn + nf * 8 + tg * 2 + 0], colsum[nf*2+0]);
            atomicAdd(&red[wn + nf * 8 + tg * 2 + 1], colsum[nf*2+1]);
        }
        __syncthreads();
        if (tid < BN) atomicAdd(&g_logit[b * T_ + n0 + tid], red[tid]);
    }
}

// ---------------- transpose + bf16 hi/lo split (both z tensors) ----------------
__global__ void transconv2_k(const float* __restrict__ Zh, const float* __restrict__ Zr)
{
    __shared__ float tile[32][33];
    const int bz = blockIdx.z;
    const int which = bz >> 5;
    const int bb = bz & 31;
    const float* Xb = ((which == 0) ? Zh : Zr) + (size_t)bb * S_ * T_;
    __nv_bfloat16* H = ((which == 0) ? g_zhT_hi : g_zrT_hi) + (size_t)bb * T_ * S_;
    __nv_bfloat16* L = ((which == 0) ? g_zhT_lo : g_zrT_lo) + (size_t)bb * T_ * S_;
    const int x0 = blockIdx.x * 32, y0 = blockIdx.y * 32;
    const int tx = threadIdx.x, ty = threadIdx.y;
#pragma unroll
    for (int j = 0; j < 4; j++)
        tile[ty + j * 8][tx] = Xb[(size_t)(y0 + ty + j * 8) * T_ + x0 + tx];
    __syncthreads();
#pragma unroll
    for (int j = 0; j < 4; j++) {
        float v = tile[tx][ty + j * 8];
        size_t o = (size_t)(x0 + ty + j * 8) * S_ + y0 + tx;
        __nv_bfloat16 h = __float2bfloat16(v);
        H[o] = h;
        L[o] = __float2bfloat16(v - __bfloat162float(h));
    }
}

__global__ void wconv_all_k(const float* __restrict__ Wb, const float* __restrict__ Wq,
                            const float* __restrict__ Wv)
{
    int i = blockIdx.x * blockDim.x + threadIdx.x;
    int which = blockIdx.y;
    const float* X = (which == 0) ? Wb : (which == 1) ? Wq : Wv;
    __nv_bfloat16* H = (which == 0) ? g_Wb_hi : (which == 1) ? g_Wq_hi : g_Wv_hi;
    __nv_bfloat16* L = (which == 0) ? g_Wb_lo : (which == 1) ? g_Wq_lo : g_Wv_lo;
    float v = X[i];
    __nv_bfloat16 h = __float2bfloat16(v);
    H[i] = h;
    L[i] = __float2bfloat16(v - __bfloat162float(h));
    if (which == 0 && i < B_ * T_) g_logit[i] = 0.0f;
}

__global__ void softmax_k(float* __restrict__ aq)
{
    __shared__ float sm[256];
    int b = blockIdx.x, tid = threadIdx.x;
    const float* lg = g_logit + b * T_;
    float v[4]; float vmax = -1e30f;
#pragma unroll
    for (int i = 0; i < 4; i++) { v[i] = lg[tid + i * 256]; vmax = fmaxf(vmax, v[i]); }
    sm[tid] = vmax; __syncthreads();
    for (int s = 128; s > 0; s >>= 1) { if (tid < s) sm[tid] = fmaxf(sm[tid], sm[tid + s]); __syncthreads(); }
    vmax = sm[0]; __syncthreads();
    float lsum = 0.0f;
#pragma unroll
    for (int i = 0; i < 4; i++) { v[i] = expf(v[i] - vmax); lsum += v[i]; }
    sm[tid] = lsum; __syncthreads();
    for (int s = 128; s > 0; s >>= 1) { if (tid < s) sm[tid] += sm[tid + s]; __syncthreads(); }
    float inv = 1.0f / sm[0];
#pragma unroll
    for (int i = 0; i < 4; i++) aq[b * T_ + tid + i * 256] = v[i] * inv;
}

__global__ void attn_k(const float* __restrict__ zr, const float* __restrict__ aq,
                       float* __restrict__ out)
{
    int gwarp = (blockIdx.x * blockDim.x + threadIdx.x) >> 5;
    int lane = threadIdx.x & 31;
    int b = gwarp >> 9, s = gwarp & (S_ - 1);
    const float* z = zr + ((size_t)b * S_ + s) * T_;
    const float* a = aq + b * T_;
    float acc = 0.0f;
#pragma unroll 4
    for (int t = lane; t < T_; t += 32) acc += z[t] * a[t];
#pragma unroll
    for (int o = 16; o > 0; o >>= 1) acc += __shfl_xor_sync(0xFFFFFFFFu, acc, o);
    if (lane == 0) out[b * S_ + s] = acc;
}

extern "C" void kernel_launch(void* const* d_in, const int* in_sizes, int n_in,
                              void* d_out, int out_size)
{
    const float* zr  = (const float*)d_in[0];
    const float* zh  = (const float*)d_in[1];
    const float* Wb  = (const float*)d_in[2];
    const float* Wq  = (const float*)d_in[3];
    const float* Wv  = (const float*)d_in[4];
    const float* whq = (const float*)d_in[5];

    float* out  = (float*)d_out;
    float* attn = out;
    float* aq   = out + B_ * S_;
    float* Cmat = out + B_ * S_ + B_ * T_;

    cudaFuncSetAttribute(mma_multi, cudaFuncAttributeMaxDynamicSharedMemorySize, GEMM_SMEM);
    cudaFuncSetAttribute(mma_gemm<EPI_TANH_HILO, 512>,  cudaFuncAttributeMaxDynamicSharedMemorySize, GEMM_SMEM);
    cudaFuncSetAttribute(mma_gemm<EPI_WG_RED, 1024>,    cudaFuncAttributeMaxDynamicSharedMemorySize, GEMM_SMEM);

    __nv_bfloat16 *zhT_hi, *zhT_lo, *zrT_hi, *zrT_lo, *auxT_hi, *auxT_lo;
    __nv_bfloat16 *C_hi, *C_lo, *a2_hi, *a2_lo;
    __nv_bfloat16 *Wb_hi, *Wb_lo, *Wq_hi, *Wq_lo, *Wv_hi, *Wv_lo;
    float *a3;
    cudaGetSymbolAddress((void**)&zhT_hi, g_zhT_hi);   cudaGetSymbolAddress((void**)&zhT_lo, g_zhT_lo);
    cudaGetSymbolAddress((void**)&zrT_hi, g_zrT_hi);   cudaGetSymbolAddress((void**)&zrT_lo, g_zrT_lo);
    cudaGetSymbolAddress((void**)&auxT_hi, g_auxT_hi); cudaGetSymbolAddress((void**)&auxT_lo, g_auxT_lo);
    cudaGetSymbolAddress((void**)&C_hi, g_C_hi);       cudaGetSymbolAddress((void**)&C_lo, g_C_lo);
    cudaGetSymbolAddress((void**)&a2_hi, g_a2_hi);     cudaGetSymbolAddress((void**)&a2_lo, g_a2_lo);
    cudaGetSymbolAddress((void**)&Wb_hi, g_Wb_hi);     cudaGetSymbolAddress((void**)&Wb_lo, g_Wb_lo);
    cudaGetSymbolAddress((void**)&Wq_hi, g_Wq_hi);     cudaGetSymbolAddress((void**)&Wq_lo, g_Wq_lo);
    cudaGetSymbolAddress((void**)&Wv_hi, g_Wv_hi);     cudaGetSymbolAddress((void**)&Wv_lo, g_Wv_lo);
    cudaGetSymbolAddress((void**)&a3, g_a3);

    const long TS = (long)T_ * S_;
    const long TT = (long)T_ * T_;
    const long FT = (long)F_ * T_;

    wconv_all_k<<<dim3((F_*S_)/256, 3), 256>>>(Wb, Wq, Wv);
    transconv2_k<<<dim3(T_/32, S_/32, 2*B_), dim3(32, 8)>>>(zh, zr);

    // Merged G1+G3+G4 (all K=512, independent); 1024 CTAs each:
    //  G1: auxT[h][s] = sum_u zhT[h][u] * Wb[s][u]   M=1024 (8 by), N=512 (4 bx)
    //  G3: aux2[f][h] = sum_s Wv[f][s] * zhT[h][s]   M=512 (4 by),  N=1024 (8 bx)
    //  G4: aux3[f][t] = sum_s Wq[f][s] * zrT[t][s]   M=512 (4 by),  N=1024 (8 bx)
    MultiDesc md;
    md.Ah[0]=zhT_hi; md.Al[0]=zhT_lo; md.Bh[0]=Wb_hi;  md.Bl[0]=Wb_lo;
    md.Dout[0]=nullptr; md.Dhi[0]=auxT_hi; md.Dlo[0]=auxT_lo;
    md.sA[0]=TS; md.sB[0]=0; md.sD[0]=TS; md.N[0]=S_; md.gxlog[0]=2; md.epi[0]=EPI_HILO;

    md.Ah[1]=Wv_hi;  md.Al[1]=Wv_lo;  md.Bh[1]=zhT_hi; md.Bl[1]=zhT_lo;
    md.Dout[1]=nullptr; md.Dhi[1]=a2_hi; md.Dlo[1]=a2_lo;
    md.sA[1]=0; md.sB[1]=TS; md.sD[1]=FT; md.N[1]=T_; md.gxlog[1]=3; md.epi[1]=EPI_HILO;

    md.Ah[2]=Wq_hi;  md.Al[2]=Wq_lo;  md.Bh[2]=zrT_hi; md.Bl[2]=zrT_lo;
    md.Dout[2]=a3; md.Dhi[2]=nullptr; md.Dlo[2]=nullptr;
    md.sA[2]=0; md.sB[2]=TS; md.sD[2]=FT; md.N[2]=T_; md.gxlog[2]=3; md.epi[2]=EPI_NONE;

    mma_multi<<<3 * 1024, 256, GEMM_SMEM>>>(md);

    // G2: C[t][h] = tanh( sum_s zrT[t][s] * auxT[h][s] )   M=N=1024, K=512
    mma_gemm<EPI_TANH_HILO, 512><<<dim3(T_/BN, T_/BM, B_), 256, GEMM_SMEM>>>(
        zrT_hi, zrT_lo, auxT_hi, auxT_lo, Cmat, C_hi, C_lo, nullptr, nullptr,
        T_, TS, TS, TT, 0L);

    // G5 fused: logits[b,t] = sum_f w_hq[f]*tanh(a3[f,t] + sum_h a2[f,h]*C[t,h])
    mma_gemm<EPI_WG_RED, 1024><<<dim3(T_/BN, F_/BM, B_), 256, GEMM_SMEM>>>(
        a2_hi, a2_lo, C_hi, C_lo, nullptr, nullptr, nullptr, a3, whq,
        T_, FT, TT, 0L, FT);

    softmax_k<<<B_, 256>>>(aq);
    attn_k<<<(B_ * S_ * 32) / 256, 256>>>(zr, aq, attn);
}